// round 11
// baseline (speedup 1.0000x reference)
#include <cuda_runtime.h>
#include <math.h>
#include <stdint.h>

#define NMAX   16384
#define SORTN  16384
#define CMAX   2
#define PIXN   2560
#define RHh    40
#define RWw    64
#define FD     17
#define SEGLEN 256
#define SEGMAX 64
#define REC    24          // floats per packed gaussian record (6 params + 17 feats + pad)
#define MSKMAX 32
#define CHUNK  4096        // elements per local-sort block

// ------------------------- device scratch (no allocation) -------------------------
__device__ float d_prep[CMAX][6][NMAX];                 // u,v,A,B,C,op
__device__ unsigned long long d_key[CMAX][SORTN];
__device__ float d_pack[CMAX][NMAX * REC];
__device__ float d_segS[CMAX][SEGMAX][FD][PIXN];
__device__ float d_segP[CMAX][SEGMAX][PIXN];
__device__ float d_fmap[CMAX][FD][PIXN];
__device__ float d_ldf[CMAX][FD][4096];
__device__ float d_proto[CMAX][MSKMAX][FD];
__device__ float d_l1part[CMAX][PIXN];
__device__ float d_bcepart[CMAX][MSKMAX];
__device__ float d_wt1[256 * 64];
__device__ float d_wt2[64 * 64];
__device__ float d_wt3[64 * 17];

// ------------------------- prep: per-gaussian camera params + sort key -------------------------
__global__ void k_prep(const float* __restrict__ xyz, const float* __restrict__ scales,
                       const float* __restrict__ rots, const float* __restrict__ opac,
                       const float* __restrict__ vm, const float* __restrict__ intr, int N)
{
    int c = blockIdx.y;
    int g = blockIdx.x * blockDim.x + threadIdx.x;
    if (g >= SORTN) return;
    if (g >= N) { d_key[c][g] = 0xFFFFFFFFFFFFFFFFull; return; }

    const float* V = vm + c * 16;
    float R00=V[0],R01=V[1],R02=V[2],T0=V[3];
    float R10=V[4],R11=V[5],R12=V[6],T1=V[7];
    float R20=V[8],R21=V[9],R22=V[10],T2=V[11];
    const float* In = intr + c * 4;
    float fx=In[0], fy=In[1], cx=In[2], cy=In[3];

    float X = xyz[g*3+0], Y = xyz[g*3+1], Z = xyz[g*3+2];
    float x = R00*X + R01*Y + R02*Z + T0;
    float y = R10*X + R11*Y + R12*Z + T1;
    float z = R20*X + R21*Y + R22*Z + T2;
    float zc = fmaxf(z, 0.001f);
    float u = fx * x / zc + cx;
    float v = fy * y / zc + cy;

    // quaternion -> rotation (normalized)
    float qw=rots[g*4+0], qx=rots[g*4+1], qy=rots[g*4+2], qz=rots[g*4+3];
    float qn = sqrtf(qw*qw + qx*qx + qy*qy + qz*qz);
    qw/=qn; qx/=qn; qy/=qn; qz/=qn;
    float Q00=1.f-2.f*(qy*qy+qz*qz), Q01=2.f*(qx*qy-qw*qz), Q02=2.f*(qx*qz+qw*qy);
    float Q10=2.f*(qx*qy+qw*qz), Q11=1.f-2.f*(qx*qx+qz*qz), Q12=2.f*(qy*qz-qw*qx);
    float Q20=2.f*(qx*qz-qw*qy), Q21=2.f*(qy*qz+qw*qx), Q22=1.f-2.f*(qx*qx+qy*qy);

    float s0 = expf(scales[g*3+0]), s1 = expf(scales[g*3+1]), s2 = expf(scales[g*3+2]);
    float M00=Q00*s0, M01=Q01*s1, M02=Q02*s2;
    float M10=Q10*s0, M11=Q11*s1, M12=Q12*s2;
    float M20=Q20*s0, M21=Q21*s1, M22=Q22*s2;

    // cov3 = M M^T (symmetric)
    float c300 = M00*M00 + M01*M01 + M02*M02;
    float c301 = M00*M10 + M01*M11 + M02*M12;
    float c302 = M00*M20 + M01*M21 + M02*M22;
    float c311 = M10*M10 + M11*M11 + M12*M12;
    float c312 = M10*M20 + M11*M21 + M12*M22;
    float c322 = M20*M20 + M21*M21 + M22*M22;

    // W = Rw * cov3
    float W00 = R00*c300 + R01*c301 + R02*c302;
    float W01 = R00*c301 + R01*c311 + R02*c312;
    float W02 = R00*c302 + R01*c312 + R02*c322;
    float W10 = R10*c300 + R11*c301 + R12*c302;
    float W11 = R10*c301 + R11*c311 + R12*c312;
    float W12 = R10*c302 + R11*c312 + R12*c322;
    float W20 = R20*c300 + R21*c301 + R22*c302;
    float W21 = R20*c301 + R21*c311 + R22*c312;
    float W22 = R20*c302 + R21*c312 + R22*c322;

    // covw = W * Rw^T (need symmetric entries)
    float cw00 = W00*R00 + W01*R01 + W02*R02;
    float cw01 = W00*R10 + W01*R11 + W02*R12;
    float cw02 = W00*R20 + W01*R21 + W02*R22;
    float cw11 = W10*R10 + W11*R11 + W12*R12;
    float cw12 = W10*R20 + W11*R21 + W12*R22;
    float cw22 = W20*R20 + W21*R21 + W22*R22;

    float iz = 1.0f / zc;
    float j00 = fx * iz, j02 = -fx * x * iz * iz;
    float j11 = fy * iz, j12 = -fy * y * iz * iz;

    float t00 = j00*cw00 + j02*cw02;
    float t01 = j00*cw01 + j02*cw12;
    float t02 = j00*cw02 + j02*cw22;
    float c2_00 = t00*j00 + t02*j02;
    float c2_01 = t01*j11 + t02*j12;
    float c2_11 = (j11*cw11 + j12*cw12)*j11 + (j11*cw12 + j12*cw22)*j12;

    float a  = c2_00 + 0.3f;
    float bq = c2_01;
    float cc = c2_11 + 0.3f;
    float det = a * cc - bq * bq;
    float A  = cc / det;
    float B  = -bq / det;
    float Cc = a / det;

    float op = opac[g] * (z > 0.2f ? 1.0f : 0.0f);

    d_prep[c][0][g] = u;  d_prep[c][1][g] = v;
    d_prep[c][2][g] = A;  d_prep[c][3][g] = B;
    d_prep[c][4][g] = Cc; d_prep[c][5][g] = op;

    unsigned int bits = __float_as_uint(z);
    unsigned int mpd  = (bits & 0x80000000u) ? ~bits : (bits | 0x80000000u);
    d_key[c][g] = ((unsigned long long)mpd << 32) | (unsigned int)g;
}

// ------------------------- parallel bitonic sort -------------------------
// Stage 1: local full bitonic sort of CHUNK-element chunks (handles k = 2..CHUNK).
// Direction uses the GLOBAL index bit so chunks compose into the global bitonic network.
__global__ void k_sort_local()
{
    int chunk = blockIdx.x, c = blockIdx.y;
    int base = chunk * CHUNK;
    __shared__ unsigned long long sk[CHUNK];
    int t = threadIdx.x;
#pragma unroll
    for (int i = t; i < CHUNK; i += 1024) sk[i] = d_key[c][base + i];
    __syncthreads();
    for (int k = 2; k <= CHUNK; k <<= 1) {
        for (int j = k >> 1; j > 0; j >>= 1) {
            int jm1 = j - 1;
#pragma unroll
            for (int m = t; m < CHUNK / 2; m += 1024) {
                int i = ((m & ~jm1) << 1) | (m & jm1);
                int l = i | j;
                bool up = (((base + i) & k) == 0);
                unsigned long long a = sk[i], b = sk[l];
                if ((a > b) == up) { sk[i] = b; sk[l] = a; }
            }
            __syncthreads();
        }
    }
#pragma unroll
    for (int i = t; i < CHUNK; i += 1024) d_key[c][base + i] = sk[i];
}

// Cross-chunk compare-swap for one (k, j) substage, j >= CHUNK.
__global__ void k_merge_global(int k, int j)
{
    int c = blockIdx.y;
    int m = blockIdx.x * blockDim.x + threadIdx.x;   // SORTN/2 pairs
    int jm1 = j - 1;
    int i = ((m & ~jm1) << 1) | (m & jm1);
    int l = i | j;
    bool up = ((i & k) == 0);
    unsigned long long a = d_key[c][i], b = d_key[c][l];
    if ((a > b) == up) { d_key[c][i] = b; d_key[c][l] = a; }
}

// Remaining substages j = CHUNK/2 .. 1 of stage k, done locally per chunk.
__global__ void k_merge_local(int k)
{
    int chunk = blockIdx.x, c = blockIdx.y;
    int base = chunk * CHUNK;
    __shared__ unsigned long long sk[CHUNK];
    int t = threadIdx.x;
#pragma unroll
    for (int i = t; i < CHUNK; i += 1024) sk[i] = d_key[c][base + i];
    __syncthreads();
    bool up = ((base & k) == 0);   // bit k is constant within a chunk (k > CHUNK)
    for (int j = CHUNK >> 1; j > 0; j >>= 1) {
        int jm1 = j - 1;
#pragma unroll
        for (int m = t; m < CHUNK / 2; m += 1024) {
            int i = ((m & ~jm1) << 1) | (m & jm1);
            int l = i | j;
            unsigned long long a = sk[i], b = sk[l];
            if ((a > b) == up) { sk[i] = b; sk[l] = a; }
        }
        __syncthreads();
    }
#pragma unroll
    for (int i = t; i < CHUNK; i += 1024) d_key[c][base + i] = sk[i];
}

// ------------------------- gather sorted params + features into packed records -------------------------
__global__ void k_pack(const float* __restrict__ vf, int N)
{
    int c = blockIdx.y;
    int g = blockIdx.x * blockDim.x + threadIdx.x;
    if (g >= N) return;
    int j = (int)(unsigned int)(d_key[c][g] & 0xFFFFFFFFull);
    float* r = &d_pack[c][g * REC];
    r[0] = d_prep[c][0][j]; r[1] = d_prep[c][1][j];
    r[2] = d_prep[c][2][j]; r[3] = d_prep[c][3][j];
    r[4] = d_prep[c][4][j]; r[5] = d_prep[c][5][j];
#pragma unroll
    for (int i = 0; i < 17; i++) r[6 + i] = vf[j * 17 + i];
    r[23] = 0.0f;
}

// ------------------------- pass A: per-segment partial compositing -------------------------
__global__ void k_passA(int N)
{
    int s = blockIdx.x, tile = blockIdx.y, c = blockIdx.z;
    int t = threadIdx.x;
    __shared__ float4 sm[SEGLEN * 6];
    int g0 = s * SEGLEN;
    int gc = min(SEGLEN, N - g0);
    const float4* src = (const float4*)&d_pack[c][g0 * REC];
    for (int i = t; i < gc * 6; i += 128) sm[i] = src[i];
    __syncthreads();

    int p = tile * 128 + t;
    float px = (float)(p % RWw), py = (float)(p / RWw);
    float T = 1.0f;
    float acc[17];
#pragma unroll
    for (int i = 0; i < 17; i++) acc[i] = 0.0f;

    for (int g = 0; g < gc; ++g) {
        float4 r0 = sm[g * 6 + 0];   // u,v,A,B
        float4 r1 = sm[g * 6 + 1];   // C,op,f0,f1
        float dx = r0.x - px, dy = r0.y - py;
        float pw = -0.5f * (r0.z * dx * dx + r1.x * dy * dy) - r0.w * dx * dy;
        // pw > -35 is a strict superset of alpha > 1e-12 for any sane opacity
        if (__any_sync(0xffffffffu, pw > -35.0f)) {
            float al = fminf(0.99f, r1.y * __expf(fminf(pw, 0.0f)));
            float w = al * T;
            acc[0]  += w * r1.z;  acc[1]  += w * r1.w;
            float4 r2 = sm[g*6+2], r3 = sm[g*6+3], r4 = sm[g*6+4], r5 = sm[g*6+5];
            acc[2]  += w * r2.x;  acc[3]  += w * r2.y;
            acc[4]  += w * r2.z;  acc[5]  += w * r2.w;
            acc[6]  += w * r3.x;  acc[7]  += w * r3.y;
            acc[8]  += w * r3.z;  acc[9]  += w * r3.w;
            acc[10] += w * r4.x;  acc[11] += w * r4.y;
            acc[12] += w * r4.z;  acc[13] += w * r4.w;
            acc[14] += w * r5.x;  acc[15] += w * r5.y;
            acc[16] += w * r5.z;
            T *= (1.0f - al);
        }
    }
#pragma unroll
    for (int i = 0; i < 17; i++) d_segS[c][s][i][p] = acc[i];
    d_segP[c][s][p] = T;
}

// ------------------------- pass B: combine segments in depth order -------------------------
__global__ void k_passB(int SEG)
{
    int idx = blockIdx.x * blockDim.x + threadIdx.x;   // over CMAX*PIXN
    int c = idx / PIXN, p = idx % PIXN;
    float T = 1.0f;
    float o[17];
#pragma unroll
    for (int i = 0; i < 17; i++) o[i] = 0.0f;
    for (int s = 0; s < SEG; s++) {
#pragma unroll
        for (int i = 0; i < 17; i++) o[i] += T * d_segS[c][s][i][p];
        T *= d_segP[c][s][p];
    }
#pragma unroll
    for (int i = 0; i < 17; i++) d_fmap[c][i][p] = o[i];
}

// ------------------------- transpose MLP weights -------------------------
__global__ void k_wt(const float* __restrict__ W1, const float* __restrict__ W2,
                     const float* __restrict__ W3)
{
    int t = blockIdx.x * blockDim.x + threadIdx.x;
    if (t < 64 * 256) { int r = t / 256, k = t % 256; d_wt1[k * 64 + r] = W1[t]; }
    if (t < 64 * 64)  { int r = t / 64,  k = t % 64;  d_wt2[k * 64 + r] = W2[t]; }
    if (t < 17 * 64)  { int r = t / 64,  k = t % 64;  d_wt3[k * 17 + r] = W3[t]; }
}

// ------------------------- 64-thread block sum -------------------------
__device__ __forceinline__ float blk64_sum(float v, float* red, int t)
{
    red[t] = v; __syncthreads();
    if (t < 32) red[t] += red[t + 32]; __syncthreads();
    if (t < 16) red[t] += red[t + 16]; __syncthreads();
    if (t < 8)  red[t] += red[t + 8];  __syncthreads();
    if (t < 4)  red[t] += red[t + 4];  __syncthreads();
    if (t < 2)  red[t] += red[t + 2];  __syncthreads();
    if (t < 1)  red[t] += red[t + 1];  __syncthreads();
    float s = red[0]; __syncthreads();
    return s;
}

// ------------------------- MLP forward for one row (64 threads) -------------------------
__device__ __forceinline__ void mlp_fwd(const float* xs, float* sc, float* red, float* out17, int t,
                                        const float* b1, const float* g1, const float* be1,
                                        const float* b2, const float* g2, const float* be2,
                                        const float* b3)
{
    float h = b1[t];
#pragma unroll 8
    for (int k = 0; k < 256; k++) h = fmaf(d_wt1[k * 64 + t], xs[k], h);
    float mu  = blk64_sum(h, red, t) * (1.0f / 64.0f);
    float d   = h - mu;
    float var = blk64_sum(d * d, red, t) * (1.0f / 64.0f);
    float hl  = d / sqrtf(var + 1e-5f) * g1[t] + be1[t];
    hl = hl > 0.0f ? hl : 0.01f * hl;
    sc[t] = hl; __syncthreads();

    float h2 = b2[t];
#pragma unroll
    for (int k = 0; k < 64; k++) h2 = fmaf(d_wt2[k * 64 + t], sc[k], h2);
    mu  = blk64_sum(h2, red, t) * (1.0f / 64.0f);
    d   = h2 - mu;
    var = blk64_sum(d * d, red, t) * (1.0f / 64.0f);
    float h2l = d / sqrtf(var + 1e-5f) * g2[t] + be2[t];
    h2l = h2l > 0.0f ? h2l : 0.01f * h2l;
    sc[t] = h2l; __syncthreads();

    if (t < 17) {
        float o = b3[t];
#pragma unroll
        for (int k = 0; k < 64; k++) o = fmaf(d_wt3[k * 17 + t], sc[k], o);
        out17[t] = o;
    }
    __syncthreads();
}

// ------------------------- sed projection + L1 partials -------------------------
__global__ void k_sed(const float* __restrict__ embd,
                      const float* b1, const float* g1, const float* be1,
                      const float* b2, const float* g2, const float* be2, const float* b3)
{
    int row = blockIdx.x;
    int c = row / PIXN, p = row % PIXN;
    int h = p / RWw, w = p % RWw;
    int ri = (int)floorf((float)h * (64.0f / 40.0f));
    __shared__ float xs[256], sc[64], red[64], out17[17];
    int t = threadIdx.x;
    const float* base = embd + (size_t)c * 256 * 4096 + (size_t)ri * 64 + w;
    for (int k = t; k < 256; k += 64) xs[k] = base[(size_t)k * 4096];
    __syncthreads();
    mlp_fwd(xs, sc, red, out17, t, b1, g1, be1, b2, g2, be2, b3);
    float v = 0.0f;
    if (t < 17) v = fabsf(d_fmap[c][t][p] - out17[t]);
    float s = blk64_sum(v, red, t);
    if (t == 0) d_l1part[c][p] = s;
}

// ------------------------- ldf projection -------------------------
__global__ void k_ldf(const float* __restrict__ feat,
                      const float* b1, const float* g1, const float* be1,
                      const float* b2, const float* g2, const float* be2, const float* b3)
{
    int row = blockIdx.x;
    int c = row / 4096, p = row % 4096;
    __shared__ float xs[256], sc[64], red[64], out17[17];
    int t = threadIdx.x;
    const float* base = feat + (size_t)c * 256 * 4096 + p;
    for (int k = t; k < 256; k += 64) xs[k] = base[(size_t)k * 4096];
    __syncthreads();
    mlp_fwd(xs, sc, red, out17, t, b1, g1, be1, b2, g2, be2, b3);
    if (t < 17) d_ldf[c][t][p] = out17[t];
}

__device__ __forceinline__ float blk256_sum(float v, float* red, int t)
{
    red[t] = v; __syncthreads();
    for (int s = 128; s > 0; s >>= 1) {
        if (t < s) red[t] += red[t + s];
        __syncthreads();
    }
    float r = red[0]; __syncthreads();
    return r;
}

// ------------------------- prototypes -------------------------
__global__ void k_proto(const float* __restrict__ masks, int Msk)
{
    int m = blockIdx.x, c = blockIdx.y;
    int t = threadIdx.x;
    const float* mb = masks + (size_t)(c * Msk + m) * 40000;
    float sums[17];
#pragma unroll
    for (int i = 0; i < 17; i++) sums[i] = 0.0f;
    float msum = 0.0f;
    for (int p = t; p < 4096; p += 256) {
        int h = p / 64, w = p % 64;
        int mi = (int)floorf((float)h * (200.0f / 64.0f));
        int mj = (int)floorf((float)w * (200.0f / 64.0f));
        float mv = mb[mi * 200 + mj];
        if (mv != 0.0f) {
            msum += mv;
#pragma unroll
            for (int i = 0; i < 17; i++) sums[i] += mv * d_ldf[c][i][p];
        }
    }
    __shared__ float red[256];
    __shared__ float res[18];
    float r0 = blk256_sum(msum, red, t);
    if (t == 0) res[0] = r0;
    for (int q = 0; q < 17; q++) {
        float rq = blk256_sum(sums[q], red, t);
        if (t == 0) res[1 + q] = rq;
    }
    __syncthreads();
    if (t < 17) d_proto[c][m][t] = res[1 + t] / fmaxf(res[0], 1e-6f);
}

// ------------------------- BCE -------------------------
__global__ void k_bce(const float* __restrict__ masks, int Msk)
{
    int m = blockIdx.x, c = blockIdx.y;
    int t = threadIdx.x;
    __shared__ float pr[17];
    if (t < 17) pr[t] = d_proto[c][m][t];
    __syncthreads();
    const float* mb = masks + (size_t)(c * Msk + m) * 40000;
    float bce = 0.0f;
    for (int p = t; p < PIXN; p += 256) {
        int h = p / RWw, w = p % RWw;
        float logit = 0.0f;
#pragma unroll
        for (int i = 0; i < 17; i++) logit += pr[i] * d_fmap[c][i][p];
        float prob = 1.0f / (1.0f + expf(-logit));
        float sr = ((float)h + 0.5f) * (200.0f / 40.0f) - 0.5f;
        float sc = ((float)w + 0.5f) * (200.0f / 64.0f) - 0.5f;
        int r0 = (int)fminf(fmaxf(floorf(sr), 0.0f), 199.0f);
        int r1 = min(r0 + 1, 199);
        float wr = fminf(fmaxf(sr - (float)r0, 0.0f), 1.0f);
        int c0 = (int)fminf(fmaxf(floorf(sc), 0.0f), 199.0f);
        int c1 = min(c0 + 1, 199);
        float wc = fminf(fmaxf(sc - (float)c0, 0.0f), 1.0f);
        float v0 = mb[r0 * 200 + c0] * (1.0f - wr) + mb[r1 * 200 + c0] * wr;
        float v1 = mb[r0 * 200 + c1] * (1.0f - wr) + mb[r1 * 200 + c1] * wr;
        float frm = v0 * (1.0f - wc) + v1 * wc;
        frm = (frm <= 0.5f) ? 0.0f : frm;
        bce += frm * logf(prob + 1e-8f) + (1.0f - frm) * logf(1.0f - prob + 1e-8f);
    }
    __shared__ float red[256];
    float s = blk256_sum(bce, red, t);
    if (t == 0) d_bcepart[c][m] = s;
}

// ------------------------- final scalar -------------------------
__global__ void k_final(float* out, int Msk)
{
    __shared__ float red[256];
    int t = threadIdx.x;
    float loss = 0.0f;
    for (int c = 0; c < 2; c++) {
        float s = 0.0f;
        for (int p = t; p < PIXN; p += 256) s += d_l1part[c][p];
        float l1 = blk256_sum(s, red, t);
        s = 0.0f;
        for (int m = t; m < Msk; m += 256) s += d_bcepart[c][m];
        float bc = blk256_sum(s, red, t);
        loss += l1 / (float)(PIXN * 17) - bc / (float)(Msk * PIXN);
    }
    if (t == 0) out[0] = loss * 0.5f;   // / C (=2) / B (=1) * weight (=1)
}

// ------------------------- launch -------------------------
extern "C" void kernel_launch(void* const* d_in, const int* in_sizes, int n_in,
                              void* d_out, int out_size)
{
    const float* vf    = (const float*)d_in[0];
    const float* opac  = (const float*)d_in[1];
    const float* embd  = (const float*)d_in[2];
    const float* feat  = (const float*)d_in[3];
    const float* masks = (const float*)d_in[4];
    const float* vm    = (const float*)d_in[5];
    const float* intr  = (const float*)d_in[6];
    const float* xyz   = (const float*)d_in[7];
    const float* scl   = (const float*)d_in[8];
    const float* rot   = (const float*)d_in[9];
    const float* W1    = (const float*)d_in[10];
    const float* b1    = (const float*)d_in[11];
    const float* g1    = (const float*)d_in[12];
    const float* be1   = (const float*)d_in[13];
    const float* W2    = (const float*)d_in[14];
    const float* b2    = (const float*)d_in[15];
    const float* g2    = (const float*)d_in[16];
    const float* be2   = (const float*)d_in[17];
    const float* W3    = (const float*)d_in[18];
    const float* b3    = (const float*)d_in[19];

    int N   = in_sizes[7] / 3;
    int Msk = in_sizes[4] / (2 * 200 * 200);
    int SEG = (N + SEGLEN - 1) / SEGLEN;

    k_wt<<<64, 256>>>(W1, W2, W3);
    k_prep<<<dim3((SORTN + 255) / 256, 2), 256>>>(xyz, scl, rot, opac, vm, intr, N);

    // parallel bitonic sort over SORTN=16384 keys per camera
    k_sort_local<<<dim3(SORTN / CHUNK, 2), 1024>>>();                    // k = 2..4096
    k_merge_global<<<dim3(SORTN / 512, 2), 256>>>(8192, 4096);           // k=8192, j=4096
    k_merge_local<<<dim3(SORTN / CHUNK, 2), 1024>>>(8192);               // k=8192, j<=2048
    k_merge_global<<<dim3(SORTN / 512, 2), 256>>>(16384, 8192);          // k=16384, j=8192
    k_merge_global<<<dim3(SORTN / 512, 2), 256>>>(16384, 4096);          // k=16384, j=4096
    k_merge_local<<<dim3(SORTN / CHUNK, 2), 1024>>>(16384);              // k=16384, j<=2048

    k_pack<<<dim3((N + 255) / 256, 2), 256>>>(vf, N);
    k_passA<<<dim3(SEG, PIXN / 128, 2), 128>>>(N);
    k_passB<<<(2 * PIXN) / 256, 256>>>(SEG);
    k_sed<<<2 * PIXN, 64>>>(embd, b1, g1, be1, b2, g2, be2, b3);
    k_ldf<<<2 * 4096, 64>>>(feat, b1, g1, be1, b2, g2, be2, b3);
    k_proto<<<dim3(Msk, 2), 256>>>(masks, Msk);
    k_bce<<<dim3(Msk, 2), 256>>>(masks, Msk);
    k_final<<<1, 256>>>((float*)d_out, Msk);
}

// round 12
// speedup vs baseline: 1.1855x; 1.1855x over previous
#include <cuda_runtime.h>
#include <math.h>
#include <stdint.h>

#define NMAX   16384
#define SORTN  16384
#define CMAX   2
#define PIXN   2560
#define RHh    40
#define RWw    64
#define FD     17
#define SEGLEN 256
#define SEGMAX 64
#define REC    24
#define MSKMAX 32
#define CHUNK  4096

// ------------------------- device scratch (no allocation) -------------------------
__device__ float d_prep[CMAX][6][NMAX];                 // u,v,A,B,C,op
__device__ unsigned long long d_key[CMAX][SORTN];
__device__ float d_pack[CMAX][NMAX * REC];
__device__ float d_segS[CMAX][SEGMAX][FD][PIXN];
__device__ float d_segP[CMAX][SEGMAX][PIXN];
__device__ float d_segT[CMAX][SEGMAX][PIXN];
__device__ float d_fmap[CMAX][FD][PIXN];
__device__ float d_ldf[CMAX][FD][4096];
__device__ float d_proto[CMAX][MSKMAX][FD];
__device__ float d_l1part[CMAX][PIXN];
__device__ float d_bcepart[CMAX][MSKMAX];
__device__ float d_wt1[256 * 64];   // [k][h]
__device__ float d_wt2[64 * 64];    // [j][h]

// ------------------------- prep (+ fused weight transpose on blockIdx.y==2) ----------
__global__ void k_prep(const float* __restrict__ xyz, const float* __restrict__ scales,
                       const float* __restrict__ rots, const float* __restrict__ opac,
                       const float* __restrict__ vm, const float* __restrict__ intr,
                       const float* __restrict__ W1, const float* __restrict__ W2, int N)
{
    if (blockIdx.y == 2) {
        int t = blockIdx.x * blockDim.x + threadIdx.x;   // 0..16383
        if (t < 64 * 256) { int r = t / 256, k = t % 256; d_wt1[k * 64 + r] = W1[t]; }
        if (t < 64 * 64)  { int r = t / 64,  k = t % 64;  d_wt2[k * 64 + r] = W2[t]; }
        return;
    }
    int c = blockIdx.y;
    int g = blockIdx.x * blockDim.x + threadIdx.x;
    if (g >= SORTN) return;
    if (g >= N) { d_key[c][g] = 0xFFFFFFFFFFFFFFFFull; return; }

    const float* V = vm + c * 16;
    float R00=V[0],R01=V[1],R02=V[2],T0=V[3];
    float R10=V[4],R11=V[5],R12=V[6],T1=V[7];
    float R20=V[8],R21=V[9],R22=V[10],T2=V[11];
    const float* In = intr + c * 4;
    float fx=In[0], fy=In[1], cx=In[2], cy=In[3];

    float X = xyz[g*3+0], Y = xyz[g*3+1], Z = xyz[g*3+2];
    float x = R00*X + R01*Y + R02*Z + T0;
    float y = R10*X + R11*Y + R12*Z + T1;
    float z = R20*X + R21*Y + R22*Z + T2;
    float zc = fmaxf(z, 0.001f);
    float u = fx * x / zc + cx;
    float v = fy * y / zc + cy;

    float qw=rots[g*4+0], qx=rots[g*4+1], qy=rots[g*4+2], qz=rots[g*4+3];
    float qn = sqrtf(qw*qw + qx*qx + qy*qy + qz*qz);
    qw/=qn; qx/=qn; qy/=qn; qz/=qn;
    float Q00=1.f-2.f*(qy*qy+qz*qz), Q01=2.f*(qx*qy-qw*qz), Q02=2.f*(qx*qz+qw*qy);
    float Q10=2.f*(qx*qy+qw*qz), Q11=1.f-2.f*(qx*qx+qz*qz), Q12=2.f*(qy*qz-qw*qx);
    float Q20=2.f*(qx*qz-qw*qy), Q21=2.f*(qy*qz+qw*qx), Q22=1.f-2.f*(qx*qx+qy*qy);

    float s0 = expf(scales[g*3+0]), s1 = expf(scales[g*3+1]), s2 = expf(scales[g*3+2]);
    float M00=Q00*s0, M01=Q01*s1, M02=Q02*s2;
    float M10=Q10*s0, M11=Q11*s1, M12=Q12*s2;
    float M20=Q20*s0, M21=Q21*s1, M22=Q22*s2;

    float c300 = M00*M00 + M01*M01 + M02*M02;
    float c301 = M00*M10 + M01*M11 + M02*M12;
    float c302 = M00*M20 + M01*M21 + M02*M22;
    float c311 = M10*M10 + M11*M11 + M12*M12;
    float c312 = M10*M20 + M11*M21 + M12*M22;
    float c322 = M20*M20 + M21*M21 + M22*M22;

    float W00 = R00*c300 + R01*c301 + R02*c302;
    float W01 = R00*c301 + R01*c311 + R02*c312;
    float W02 = R00*c302 + R01*c312 + R02*c322;
    float W10 = R10*c300 + R11*c301 + R12*c302;
    float W11 = R10*c301 + R11*c311 + R12*c312;
    float W12 = R10*c302 + R11*c312 + R12*c322;
    float W20 = R20*c300 + R21*c301 + R22*c302;
    float W21 = R20*c301 + R21*c311 + R22*c312;
    float W22 = R20*c302 + R21*c312 + R22*c322;

    float cw00 = W00*R00 + W01*R01 + W02*R02;
    float cw01 = W00*R10 + W01*R11 + W02*R12;
    float cw02 = W00*R20 + W01*R21 + W02*R22;
    float cw11 = W10*R10 + W11*R11 + W12*R12;
    float cw12 = W10*R20 + W11*R21 + W12*R22;
    float cw22 = W20*R20 + W21*R21 + W22*R22;

    float iz = 1.0f / zc;
    float j00 = fx * iz, j02 = -fx * x * iz * iz;
    float j11 = fy * iz, j12 = -fy * y * iz * iz;

    float t00 = j00*cw00 + j02*cw02;
    float t01 = j00*cw01 + j02*cw12;
    float t02 = j00*cw02 + j02*cw22;
    float c2_00 = t00*j00 + t02*j02;
    float c2_01 = t01*j11 + t02*j12;
    float c2_11 = (j11*cw11 + j12*cw12)*j11 + (j11*cw12 + j12*cw22)*j12;

    float a  = c2_00 + 0.3f;
    float bq = c2_01;
    float cc = c2_11 + 0.3f;
    float det = a * cc - bq * bq;
    float A  = cc / det;
    float B  = -bq / det;
    float Cc = a / det;

    float op = opac[g] * (z > 0.2f ? 1.0f : 0.0f);

    d_prep[c][0][g] = u;  d_prep[c][1][g] = v;
    d_prep[c][2][g] = A;  d_prep[c][3][g] = B;
    d_prep[c][4][g] = Cc; d_prep[c][5][g] = op;

    unsigned int bits = __float_as_uint(z);
    unsigned int mpd  = (bits & 0x80000000u) ? ~bits : (bits | 0x80000000u);
    d_key[c][g] = ((unsigned long long)mpd << 32) | (unsigned int)g;
}

// ------------------------- parallel bitonic sort -------------------------
__global__ void k_sort_local()
{
    int chunk = blockIdx.x, c = blockIdx.y;
    int base = chunk * CHUNK;
    __shared__ unsigned long long sk[CHUNK];
    int t = threadIdx.x;
    for (int i = t; i < CHUNK; i += 1024) sk[i] = d_key[c][base + i];
    __syncthreads();
    for (int k = 2; k <= CHUNK; k <<= 1) {
        for (int j = k >> 1; j > 0; j >>= 1) {
            int jm1 = j - 1;
            for (int m = t; m < CHUNK / 2; m += 1024) {
                int i = ((m & ~jm1) << 1) | (m & jm1);
                int l = i | j;
                bool up = (((base + i) & k) == 0);
                unsigned long long a = sk[i], b = sk[l];
                if ((a > b) == up) { sk[i] = b; sk[l] = a; }
            }
            __syncthreads();
        }
    }
    for (int i = t; i < CHUNK; i += 1024) d_key[c][base + i] = sk[i];
}

// Full merge stage k done in one smem window of `span` elements (span*8 bytes dyn smem).
__global__ void k_merge_smem(int k, int span)
{
    extern __shared__ unsigned long long sk[];
    int c = blockIdx.y;
    int base = blockIdx.x * span;
    int t = threadIdx.x;
    for (int i = t; i < span; i += 1024) sk[i] = d_key[c][base + i];
    __syncthreads();
    for (int j = span >> 1; j > 0; j >>= 1) {
        int jm1 = j - 1;
        for (int m = t; m < (span >> 1); m += 1024) {
            int i = ((m & ~jm1) << 1) | (m & jm1);
            int l = i | j;
            bool up = (((base + i) & k) == 0);
            unsigned long long a = sk[i], b = sk[l];
            if ((a > b) == up) { sk[i] = b; sk[l] = a; }
        }
        __syncthreads();
    }
    for (int i = t; i < span; i += 1024) d_key[c][base + i] = sk[i];
}

// ------------------------- gather sorted params + features -------------------------
__global__ void k_pack(const float* __restrict__ vf, int N)
{
    int c = blockIdx.y;
    int g = blockIdx.x * blockDim.x + threadIdx.x;
    if (g >= N) return;
    int j = (int)(unsigned int)(d_key[c][g] & 0xFFFFFFFFull);
    float* r = &d_pack[c][g * REC];
    r[0] = d_prep[c][0][j]; r[1] = d_prep[c][1][j];
    r[2] = d_prep[c][2][j]; r[3] = d_prep[c][3][j];
    r[4] = d_prep[c][4][j]; r[5] = d_prep[c][5][j];
#pragma unroll
    for (int i = 0; i < 17; i++) r[6 + i] = vf[j * 17 + i];
    r[23] = 0.0f;
}

// ------------------------- pass A: per-segment partial compositing (8x4 warp tiles) ---
__global__ void k_passA(int N)
{
    int s = blockIdx.x, tile = blockIdx.y, c = blockIdx.z;
    int t = threadIdx.x;
    __shared__ float4 sm[SEGLEN * 6];
    int g0 = s * SEGLEN;
    int gc = min(SEGLEN, N - g0);
    const float4* src = (const float4*)&d_pack[c][g0 * REC];
    for (int i = t; i < gc * 6; i += 128) sm[i] = src[i];
    __syncthreads();

    // block covers a 16x8 patch; each warp an 8x4 sub-patch (tight footprint -> fewer ballot hits)
    int tx = tile & 3, ty = tile >> 2;            // 4 x 5 tiles of 16x8
    int lane = t & 31, wrp = t >> 5;
    int lx = lane & 7, ly = lane >> 3;            // 8 x 4 within warp
    int wx = wrp & 1, wy = wrp >> 1;              // 2 x 2 warps within block
    int pxi = tx * 16 + wx * 8 + lx;
    int pyi = ty * 8 + wy * 4 + ly;
    int p = pyi * RWw + pxi;
    float px = (float)pxi, py = (float)pyi;

    float T = 1.0f;
    float acc[17];
#pragma unroll
    for (int i = 0; i < 17; i++) acc[i] = 0.0f;

    for (int g = 0; g < gc; ++g) {
        float4 r0 = sm[g * 6 + 0];   // u,v,A,B
        float4 r1 = sm[g * 6 + 1];   // C,op,f0,f1
        float dx = r0.x - px, dy = r0.y - py;
        float pw = -0.5f * (r0.z * dx * dx + r1.x * dy * dy) - r0.w * dx * dy;
        if (__any_sync(0xffffffffu, pw > -35.0f)) {
            float al = fminf(0.99f, r1.y * __expf(fminf(pw, 0.0f)));
            float w = al * T;
            acc[0]  += w * r1.z;  acc[1]  += w * r1.w;
            float4 r2 = sm[g*6+2], r3 = sm[g*6+3], r4 = sm[g*6+4], r5 = sm[g*6+5];
            acc[2]  += w * r2.x;  acc[3]  += w * r2.y;
            acc[4]  += w * r2.z;  acc[5]  += w * r2.w;
            acc[6]  += w * r3.x;  acc[7]  += w * r3.y;
            acc[8]  += w * r3.z;  acc[9]  += w * r3.w;
            acc[10] += w * r4.x;  acc[11] += w * r4.y;
            acc[12] += w * r4.z;  acc[13] += w * r4.w;
            acc[14] += w * r5.x;  acc[15] += w * r5.y;
            acc[16] += w * r5.z;
            T *= (1.0f - al);
        }
    }
#pragma unroll
    for (int i = 0; i < 17; i++) d_segS[c][s][i][p] = acc[i];
    d_segP[c][s][p] = T;
}

// ------------------------- pass T: exclusive transmittance prefix per pixel ----------
__global__ void k_passT(int SEG)
{
    int idx = blockIdx.x * blockDim.x + threadIdx.x;
    if (idx >= CMAX * PIXN) return;
    int c = idx / PIXN, p = idx % PIXN;
    float T = 1.0f;
    for (int s = 0; s < SEG; s++) {
        d_segT[c][s][p] = T;
        T *= d_segP[c][s][p];
    }
}

// ------------------------- pass F: combine segments (parallel over c,i,p) ------------
__global__ void k_passF(int SEG)
{
    int p = blockIdx.x * blockDim.x + threadIdx.x;
    int i = blockIdx.y, c = blockIdx.z;
    float o = 0.0f;
    for (int s = 0; s < SEG; s++)
        o = fmaf(d_segT[c][s][p], d_segS[c][s][i][p], o);
    d_fmap[c][i][p] = o;
}

// ------------------------- fused MLP (ldf + sed), one thread per pixel ---------------
__global__ void __launch_bounds__(128, 1)
k_mlp(const float* __restrict__ embd, const float* __restrict__ feat,
      const float* __restrict__ b1, const float* __restrict__ g1, const float* __restrict__ be1,
      const float* __restrict__ b2, const float* __restrict__ g2, const float* __restrict__ be2,
      const float* __restrict__ W3, const float* __restrict__ b3)
{
    extern __shared__ float smf[];
    float* w1s = smf;              // 16384  [k][h]
    float* w2s = smf + 16384;      // 4096   [j][h]
    float* w3s = smf + 20480;      // 1088   [i][j]
    float* bb  = smf + 21568;      // 6*64 + 17

    int t = threadIdx.x;
    {
        const float4* s1 = (const float4*)d_wt1;
        float4* t1 = (float4*)w1s;
        for (int i = t; i < 4096; i += 128) t1[i] = s1[i];
        const float4* s2 = (const float4*)d_wt2;
        float4* t2 = (float4*)w2s;
        for (int i = t; i < 1024; i += 128) t2[i] = s2[i];
        for (int i = t; i < 1088; i += 128) w3s[i] = W3[i];
        if (t < 64) {
            bb[t] = b1[t]; bb[64+t] = g1[t]; bb[128+t] = be1[t];
            bb[192+t] = b2[t]; bb[256+t] = g2[t]; bb[320+t] = be2[t];
        }
        if (t < 17) bb[384+t] = b3[t];
    }
    __syncthreads();

    int row = blockIdx.x * 128 + t;   // 0..13311 : [0,8192)=ldf, [8192,13312)=sed
    int c, p; const float* xb; bool sed;
    if (row < 8192) {
        sed = false; c = row >> 12; p = row & 4095;
        xb = feat + (size_t)c * 1048576 + p;
    } else {
        sed = true; int r = row - 8192;
        c = (r >= PIXN) ? 1 : 0; p = r - c * PIXN;
        int hh = p >> 6, ww = p & 63;
        int ri = (int)floorf((float)hh * (64.0f / 40.0f));
        xb = embd + (size_t)c * 1048576 + ri * 64 + ww;
    }

    // ---- layer 1: h1 = X @ W1^T + b1 ----
    float h1[64];
#pragma unroll
    for (int h = 0; h < 64; h++) h1[h] = bb[h];
#pragma unroll 4
    for (int k = 0; k < 256; k++) {
        float x = xb[(size_t)k * 4096];
        const float4* wr = (const float4*)(w1s + k * 64);
#pragma unroll
        for (int q = 0; q < 16; q++) {
            float4 w4 = wr[q];
            h1[4*q+0] = fmaf(w4.x, x, h1[4*q+0]);
            h1[4*q+1] = fmaf(w4.y, x, h1[4*q+1]);
            h1[4*q+2] = fmaf(w4.z, x, h1[4*q+2]);
            h1[4*q+3] = fmaf(w4.w, x, h1[4*q+3]);
        }
    }
    // layernorm + leaky relu (per-thread, no syncs)
    {
        float mu = 0.0f;
#pragma unroll
        for (int h = 0; h < 64; h++) mu += h1[h];
        mu *= (1.0f / 64.0f);
        float var = 0.0f;
#pragma unroll
        for (int h = 0; h < 64; h++) { float d = h1[h] - mu; var = fmaf(d, d, var); }
        var *= (1.0f / 64.0f);
        float is = 1.0f / sqrtf(var + 1e-5f);
#pragma unroll
        for (int h = 0; h < 64; h++) {
            float v = (h1[h] - mu) * is * bb[64+h] + bb[128+h];
            h1[h] = v > 0.0f ? v : 0.01f * v;
        }
    }

    // ---- layer 2 ----
    float h2[64];
#pragma unroll
    for (int h = 0; h < 64; h++) h2[h] = bb[192+h];
#pragma unroll
    for (int j = 0; j < 64; j++) {
        float xj = h1[j];
        const float4* wr = (const float4*)(w2s + j * 64);
#pragma unroll
        for (int q = 0; q < 16; q++) {
            float4 w4 = wr[q];
            h2[4*q+0] = fmaf(w4.x, xj, h2[4*q+0]);
            h2[4*q+1] = fmaf(w4.y, xj, h2[4*q+1]);
            h2[4*q+2] = fmaf(w4.z, xj, h2[4*q+2]);
            h2[4*q+3] = fmaf(w4.w, xj, h2[4*q+3]);
        }
    }
    {
        float mu = 0.0f;
#pragma unroll
        for (int h = 0; h < 64; h++) mu += h2[h];
        mu *= (1.0f / 64.0f);
        float var = 0.0f;
#pragma unroll
        for (int h = 0; h < 64; h++) { float d = h2[h] - mu; var = fmaf(d, d, var); }
        var *= (1.0f / 64.0f);
        float is = 1.0f / sqrtf(var + 1e-5f);
#pragma unroll
        for (int h = 0; h < 64; h++) {
            float v = (h2[h] - mu) * is * bb[256+h] + bb[320+h];
            h2[h] = v > 0.0f ? v : 0.01f * v;
        }
    }

    // ---- layer 3 (17 outputs) ----
    if (!sed) {
#pragma unroll
        for (int i = 0; i < 17; i++) {
            float acc = bb[384+i];
            const float4* wr = (const float4*)(w3s + i * 64);
#pragma unroll
            for (int q = 0; q < 16; q++) {
                float4 w4 = wr[q];
                acc = fmaf(w4.x, h2[4*q+0], acc);
                acc = fmaf(w4.y, h2[4*q+1], acc);
                acc = fmaf(w4.z, h2[4*q+2], acc);
                acc = fmaf(w4.w, h2[4*q+3], acc);
            }
            d_ldf[c][i][p] = acc;
        }
    } else {
        float s = 0.0f;
#pragma unroll
        for (int i = 0; i < 17; i++) {
            float acc = bb[384+i];
            const float4* wr = (const float4*)(w3s + i * 64);
#pragma unroll
            for (int q = 0; q < 16; q++) {
                float4 w4 = wr[q];
                acc = fmaf(w4.x, h2[4*q+0], acc);
                acc = fmaf(w4.y, h2[4*q+1], acc);
                acc = fmaf(w4.z, h2[4*q+2], acc);
                acc = fmaf(w4.w, h2[4*q+3], acc);
            }
            s += fabsf(d_fmap[c][i][p] - acc);
        }
        d_l1part[c][p] = s;
    }
}

__device__ __forceinline__ float blk256_sum(float v, float* red, int t)
{
    red[t] = v; __syncthreads();
    for (int s = 128; s > 0; s >>= 1) {
        if (t < s) red[t] += red[t + s];
        __syncthreads();
    }
    float r = red[0]; __syncthreads();
    return r;
}

// ------------------------- prototypes -------------------------
__global__ void k_proto(const float* __restrict__ masks, int Msk)
{
    int m = blockIdx.x, c = blockIdx.y;
    int t = threadIdx.x;
    const float* mb = masks + (size_t)(c * Msk + m) * 40000;
    float sums[17];
#pragma unroll
    for (int i = 0; i < 17; i++) sums[i] = 0.0f;
    float msum = 0.0f;
    for (int p = t; p < 4096; p += 256) {
        int h = p / 64, w = p % 64;
        int mi = (int)floorf((float)h * (200.0f / 64.0f));
        int mj = (int)floorf((float)w * (200.0f / 64.0f));
        float mv = mb[mi * 200 + mj];
        if (mv != 0.0f) {
            msum += mv;
#pragma unroll
            for (int i = 0; i < 17; i++) sums[i] += mv * d_ldf[c][i][p];
        }
    }
    __shared__ float red[256];
    __shared__ float res[18];
    float r0 = blk256_sum(msum, red, t);
    if (t == 0) res[0] = r0;
    for (int q = 0; q < 17; q++) {
        float rq = blk256_sum(sums[q], red, t);
        if (t == 0) res[1 + q] = rq;
    }
    __syncthreads();
    if (t < 17) d_proto[c][m][t] = res[1 + t] / fmaxf(res[0], 1e-6f);
}

// ------------------------- BCE -------------------------
__global__ void k_bce(const float* __restrict__ masks, int Msk)
{
    int m = blockIdx.x, c = blockIdx.y;
    int t = threadIdx.x;
    __shared__ float pr[17];
    if (t < 17) pr[t] = d_proto[c][m][t];
    __syncthreads();
    const float* mb = masks + (size_t)(c * Msk + m) * 40000;
    float bce = 0.0f;
    for (int p = t; p < PIXN; p += 256) {
        int h = p / RWw, w = p % RWw;
        float logit = 0.0f;
#pragma unroll
        for (int i = 0; i < 17; i++) logit += pr[i] * d_fmap[c][i][p];
        float prob = 1.0f / (1.0f + expf(-logit));
        float sr = ((float)h + 0.5f) * (200.0f / 40.0f) - 0.5f;
        float sc = ((float)w + 0.5f) * (200.0f / 64.0f) - 0.5f;
        int r0 = (int)fminf(fmaxf(floorf(sr), 0.0f), 199.0f);
        int r1 = min(r0 + 1, 199);
        float wr = fminf(fmaxf(sr - (float)r0, 0.0f), 1.0f);
        int c0 = (int)fminf(fmaxf(floorf(sc), 0.0f), 199.0f);
        int c1 = min(c0 + 1, 199);
        float wc = fminf(fmaxf(sc - (float)c0, 0.0f), 1.0f);
        float v0 = mb[r0 * 200 + c0] * (1.0f - wr) + mb[r1 * 200 + c0] * wr;
        float v1 = mb[r0 * 200 + c1] * (1.0f - wr) + mb[r1 * 200 + c1] * wr;
        float frm = v0 * (1.0f - wc) + v1 * wc;
        frm = (frm <= 0.5f) ? 0.0f : frm;
        bce += frm * logf(prob + 1e-8f) + (1.0f - frm) * logf(1.0f - prob + 1e-8f);
    }
    __shared__ float red[256];
    float s = blk256_sum(bce, red, t);
    if (t == 0) d_bcepart[c][m] = s;
}

// ------------------------- final scalar -------------------------
__global__ void k_final(float* out, int Msk)
{
    __shared__ float red[256];
    int t = threadIdx.x;
    float loss = 0.0f;
    for (int c = 0; c < 2; c++) {
        float s = 0.0f;
        for (int p = t; p < PIXN; p += 256) s += d_l1part[c][p];
        float l1 = blk256_sum(s, red, t);
        s = 0.0f;
        for (int m = t; m < Msk; m += 256) s += d_bcepart[c][m];
        float bc = blk256_sum(s, red, t);
        loss += l1 / (float)(PIXN * 17) - bc / (float)(Msk * PIXN);
    }
    if (t == 0) out[0] = loss * 0.5f;
}

// ------------------------- launch -------------------------
extern "C" void kernel_launch(void* const* d_in, const int* in_sizes, int n_in,
                              void* d_out, int out_size)
{
    const float* vf    = (const float*)d_in[0];
    const float* opac  = (const float*)d_in[1];
    const float* embd  = (const float*)d_in[2];
    const float* feat  = (const float*)d_in[3];
    const float* masks = (const float*)d_in[4];
    const float* vm    = (const float*)d_in[5];
    const float* intr  = (const float*)d_in[6];
    const float* xyz   = (const float*)d_in[7];
    const float* scl   = (const float*)d_in[8];
    const float* rot   = (const float*)d_in[9];
    const float* W1    = (const float*)d_in[10];
    const float* b1    = (const float*)d_in[11];
    const float* g1    = (const float*)d_in[12];
    const float* be1   = (const float*)d_in[13];
    const float* W2    = (const float*)d_in[14];
    const float* b2    = (const float*)d_in[15];
    const float* g2    = (const float*)d_in[16];
    const float* be2   = (const float*)d_in[17];
    const float* W3    = (const float*)d_in[18];
    const float* b3    = (const float*)d_in[19];

    int N   = in_sizes[7] / 3;
    int Msk = in_sizes[4] / (2 * 200 * 200);
    int SEG = (N + SEGLEN - 1) / SEGLEN;

    k_prep<<<dim3(64, 3), 256>>>(xyz, scl, rot, opac, vm, intr, W1, W2, N);

    // sort: local chunks, then each full merge stage inside one smem window
    k_sort_local<<<dim3(SORTN / CHUNK, 2), 1024>>>();
    cudaFuncSetAttribute(k_merge_smem, cudaFuncAttributeMaxDynamicSharedMemorySize, 131072);
    k_merge_smem<<<dim3(2, 2), 1024, 8192 * 8>>>(8192, 8192);
    k_merge_smem<<<dim3(1, 2), 1024, 16384 * 8>>>(16384, 16384);

    k_pack<<<dim3((N + 255) / 256, 2), 256>>>(vf, N);
    k_passA<<<dim3(SEG, 20, 2), 128>>>(N);
    k_passT<<<(CMAX * PIXN + 127) / 128, 128>>>(SEG);
    k_passF<<<dim3(PIXN / 128, FD, CMAX), 128>>>(SEG);

    cudaFuncSetAttribute(k_mlp, cudaFuncAttributeMaxDynamicSharedMemorySize, 90000);
    k_mlp<<<104, 128, 21985 * 4>>>(embd, feat, b1, g1, be1, b2, g2, be2, W3, b3);

    k_proto<<<dim3(Msk, 2), 256>>>(masks, Msk);
    k_bce<<<dim3(Msk, 2), 256>>>(masks, Msk);
    k_final<<<1, 256>>>((float*)d_out, Msk);
}